// round 12
// baseline (speedup 1.0000x reference)
#include <cuda_runtime.h>
#include <math.h>

// Problem constants (fixed by the reference setup)
#define Bd   128
#define Vd   4
#define Dd   128
#define Nd   512           // B*V
#define ANCH 4             // anchors per block
#define GRID (Nd / ANCH)   // 128 blocks
#define NT   512           // threads per block
#define NW   16            // warps
#define WR   16            // rows per warp per tile
#define TILE 256           // rows per tile
#define NTIL (Nd / TILE)   // 2 tiles
#define RS   136           // padded row stride; mid-row pad at 68 (conflict-free)
#define MID  68            // k-half 1 starts at float 68 within a row
#define PMAX 64            // max positives per anchor (padded)

#define SM_ROWS (NW * WR * RS)   // warp-private row buffers
#define SM_SA   (ANCH * RS)      // anchor rows (same padded layout)
#define SM_SDM  (ANCH * Nd)
#define DYN_BYTES ((SM_ROWS + SM_SA + SM_SDM) * 4)

#define INF_F __int_as_float(0x7f800000)

// Scratch (device globals — no allocation allowed)
__device__ float        g_part[GRID];
__device__ unsigned int g_cntp[GRID];
__device__ unsigned int g_done = 0;

// packed fp32x2 helpers
__device__ __forceinline__ void fma2(unsigned long long& acc,
                                     unsigned long long a,
                                     unsigned long long b) {
    asm("fma.rn.f32x2 %0, %1, %2, %0;" : "+l"(acc) : "l"(a), "l"(b));
}
__device__ __forceinline__ float sum2(unsigned long long v) {
    float lo, hi;
    asm("mov.b64 {%0,%1}, %2;" : "=f"(lo), "=f"(hi) : "l"(v));
    return lo + hi;
}

// padded store index for float d within a row (halves at 0 and MID)
static __device__ __forceinline__ int pidx(int d) {
    return (d & 63) + (d >> 6) * MID;
}

__global__ void __launch_bounds__(NT, 1)
fused_triplet_kernel(const float* __restrict__ feat,
                     const int*   __restrict__ labels,
                     float*       __restrict__ out) {
    extern __shared__ float smem[];
    float* rows = smem;                 // NW * WR * RS (warp w at w*WR*RS)
    float* sa   = rows + SM_ROWS;       // ANCH * RS
    float* sdm  = sa + SM_SA;           // ANCH * Nd

    __shared__ int          slab[Nd];
    __shared__ float        spp[ANCH][PMAX];
    __shared__ float        srt[ANCH][PMAX];
    __shared__ float        sfx[ANCH][PMAX];
    __shared__ int          snpos[ANCH];
    __shared__ float        s_invna[ANCH];
    __shared__ float        swsum[NW];
    __shared__ unsigned int swcnt[NW];
    __shared__ int          sIsLast;

    const int t    = threadIdx.x;
    const int w    = t >> 5;
    const int lane = t & 31;
    const int blk  = blockIdx.x;

    // row n of emb <- features[n & 127, n >> 7, :]
    auto row_ptr = [&](int n) -> const float* {
        return feat + (size_t)(n & (Bd - 1)) * (Vd * Dd) + (n >> 7) * Dd;
    };

    float* wbuf = rows + w * WR * RS;   // this warp's 16-row buffer

    // ---- stage tile 0 rows w*16..w*16+15 (coalesced LDG, padded STS) ----
#pragma unroll
    for (int rr = 0; rr < WR; rr++) {
        int lrow = w * WR + rr;
        float4 v = reinterpret_cast<const float4*>(row_ptr(lrow))[lane];
        *reinterpret_cast<float4*>(wbuf + rr * RS + pidx(lane * 4)) = v;
    }

    // ---- anchors into shared (padded layout) + labels ----
    slab[t] = labels[t & (Bd - 1)];
    if (t < ANCH * Dd) {
        int i = t >> 7;
        int d = t & (Dd - 1);
        sa[i * RS + pidx(d)] = row_ptr(blk * ANCH + i)[d];
    }
    if (t < ANCH) snpos[t] = 0;
    if (t < ANCH * PMAX) srt[t >> 6][t & 63] = INF_F;
    __syncthreads();   // sa + slab visible (row buffers are warp-private)

    // anchor inverse norms (warps 0..3 read padded sa)
    if (w < ANCH) {
        float4 v = *reinterpret_cast<const float4*>(
            sa + w * RS + (lane & 15) * 4 + (lane >> 4) * MID);
        float s = v.x * v.x + v.y * v.y + v.z * v.z + v.w * v.w;
#pragma unroll
        for (int o = 16; o > 0; o >>= 1) s += __shfl_xor_sync(0xffffffffu, s, o);
        if (lane == 0) s_invna[w] = rsqrtf(s);
    }
    __syncthreads();   // s_invna visible

    const int kh = lane & 1;    // k-half (partner = lane^1)
    const int rl = lane >> 1;   // row within warp's 16

    const ulonglong2* a0p = reinterpret_cast<const ulonglong2*>(sa + 0 * RS + kh * MID);
    const ulonglong2* a1p = reinterpret_cast<const ulonglong2*>(sa + 1 * RS + kh * MID);
    const ulonglong2* a2p = reinterpret_cast<const ulonglong2*>(sa + 2 * RS + kh * MID);
    const ulonglong2* a3p = reinterpret_cast<const ulonglong2*>(sa + 3 * RS + kh * MID);
    const ulonglong2* rowp =
        reinterpret_cast<const ulonglong2*>(wbuf + rl * RS + kh * MID);

    const float ina0 = s_invna[0];
    const float ina1 = s_invna[1];
    const float ina2 = s_invna[2];
    const float ina3 = s_invna[3];

    // ---- compute this warp's 16-row slice (combine halves via shfl^1) ----
    // 64 floats per k-half = 16 ulonglong2 chunks
    auto compute_tile = [&](int gbase) {
        unsigned long long c0a=0,c0b=0,c1a=0,c1b=0,c2a=0,c2b=0,
                           c3a=0,c3b=0,c4a=0,c4b=0;
#pragma unroll
        for (int c = 0; c < 16; c++) {
            ulonglong2 f  = rowp[c];
            ulonglong2 a0 = a0p[c];
            ulonglong2 a1 = a1p[c];
            ulonglong2 a2 = a2p[c];
            ulonglong2 a3 = a3p[c];
            fma2(c0a, f.x, a0.x);  fma2(c0b, f.y, a0.y);
            fma2(c1a, f.x, a1.x);  fma2(c1b, f.y, a1.y);
            fma2(c2a, f.x, a2.x);  fma2(c2b, f.y, a2.y);
            fma2(c3a, f.x, a3.x);  fma2(c3b, f.y, a3.y);
            fma2(c4a, f.x, f.x);   fma2(c4b, f.y, f.y);
        }
        float d0 = sum2(c0a) + sum2(c0b);
        float d1 = sum2(c1a) + sum2(c1b);
        float d2 = sum2(c2a) + sum2(c2b);
        float d3 = sum2(c3a) + sum2(c3b);
        float sq = sum2(c4a) + sum2(c4b);
        d0 += __shfl_xor_sync(0xffffffffu, d0, 1);
        d1 += __shfl_xor_sync(0xffffffffu, d1, 1);
        d2 += __shfl_xor_sync(0xffffffffu, d2, 1);
        d3 += __shfl_xor_sync(0xffffffffu, d3, 1);
        sq += __shfl_xor_sync(0xffffffffu, sq, 1);

        float invnj = rsqrtf(sq);
        int gj = gbase + rl;
        if (kh == 0) {
            float s0 = fmaxf(2.f - 2.f * (d0 * ina0 * invnj), 0.f);
            float s1 = fmaxf(2.f - 2.f * (d1 * ina1 * invnj), 0.f);
            sdm[0 * Nd + gj] = (s0 > 0.f) ? s0 * rsqrtf(s0) : 0.f;
            sdm[1 * Nd + gj] = (s1 > 0.f) ? s1 * rsqrtf(s1) : 0.f;
        } else {
            float s2 = fmaxf(2.f - 2.f * (d2 * ina2 * invnj), 0.f);
            float s3 = fmaxf(2.f - 2.f * (d3 * ina3 * invnj), 0.f);
            sdm[2 * Nd + gj] = (s2 > 0.f) ? s2 * rsqrtf(s2) : 0.f;
            sdm[3 * Nd + gj] = (s3 > 0.f) ? s3 * rsqrtf(s3) : 0.f;
        }
    };

    compute_tile(0 * TILE + w * WR);      // tile 0 (warp-local data)
    __syncwarp();

    // ---- restage tile 1 rows (warp-private, no block barrier) ----
#pragma unroll
    for (int rr = 0; rr < WR; rr++) {
        int lrow = TILE + w * WR + rr;
        float4 v = reinterpret_cast<const float4*>(row_ptr(lrow))[lane];
        *reinterpret_cast<float4*>(wbuf + rr * RS + pidx(lane * 4)) = v;
    }
    __syncwarp();
    compute_tile(1 * TILE + w * WR);      // tile 1
    __syncthreads();                      // sdm complete

    // ---- gather positive distances per anchor (atomic append) ----
    {
        int myl = slab[t];
#pragma unroll
        for (int i = 0; i < ANCH; i++) {
            int a = blk * ANCH + i;
            if (myl == slab[a] && t != a) {
                int k = atomicAdd(&snpos[i], 1);
                if (k < PMAX) spp[i][k] = sdm[i * Nd + t];
            }
        }
    }
    __syncthreads();

    // ---- rank-sort positives ascending into srt (INF padded) ----
    if (t < ANCH * PMAX) {
        int i = t >> 6, q = t & 63;
        int P = min(snpos[i], PMAX);
        if (q < P) {
            float v = spp[i][q];
            int rk = 0;
            for (int j = 0; j < P; j++) {
                float u = spp[i][j];
                rk += (u < v) || (u == v && j < q);
            }
            srt[i][rk] = v;
        }
    }
    __syncthreads();

    // ---- suffix sums via reversed warp prefix-scan (warp i -> anchor i) ----
    if (w < ANCH) {
        int P = min(snpos[w], PMAX);
        int j0 = lane, j1 = 32 + lane;
        float x0 = (63 - j0 < P) ? srt[w][63 - j0] : 0.f;
        float x1 = (63 - j1 < P) ? srt[w][63 - j1] : 0.f;
        float s0 = x0, s1 = x1;
#pragma unroll
        for (int o = 1; o < 32; o <<= 1) {
            float v = __shfl_up_sync(0xffffffffu, s0, o);
            if (lane >= o) s0 += v;
        }
        float tot0 = __shfl_sync(0xffffffffu, s0, 31);
#pragma unroll
        for (int o = 1; o < 32; o <<= 1) {
            float v = __shfl_up_sync(0xffffffffu, s1, o);
            if (lane >= o) s1 += v;
        }
        s1 += tot0;
        sfx[w][63 - j0] = s0;   // sfx[k] = sum_{j>=k, j<P} srt[j]
        sfx[w][31 - lane] = s1;
    }
    __syncthreads();

    // ---- triplet reduction: thread t = negative n; binary search per anchor ----
    float        lsum = 0.0f;
    unsigned int lcnt = 0;
    {
        int myl = slab[t];
#pragma unroll
        for (int i = 0; i < ANCH; i++) {
            int a = blk * ANCH + i;
            if (myl != slab[a]) {
                float dan = sdm[i * Nd + t];
                int P = min(snpos[i], PMAX);
                int lo = 0;   // count of positives <= dan
#pragma unroll
                for (int s = 32; s > 0; s >>= 1)
                    if (srt[i][lo + s - 1] <= dan) lo += s;
                int cg = P - lo;                  // positives with d_ap > d_an
                lsum += sfx[i][lo] - (float)cg * dan;
                lcnt += (unsigned)cg;
            }
        }
    }

    // ---- block reduce (sum, count) ----
#pragma unroll
    for (int o = 16; o > 0; o >>= 1) {
        lsum += __shfl_xor_sync(0xffffffffu, lsum, o);
        lcnt += __shfl_xor_sync(0xffffffffu, lcnt, o);
    }
    if (lane == 0) { swsum[w] = lsum; swcnt[w] = lcnt; }
    __syncthreads();

    if (t == 0) {
        float bs = 0.0f; unsigned int bc = 0;
#pragma unroll
        for (int k = 0; k < NW; k++) { bs += swsum[k]; bc += swcnt[k]; }
        g_part[blk] = bs;
        g_cntp[blk] = bc;
        __threadfence();
        unsigned int old = atomicAdd(&g_done, 1);
        sIsLast = (old == GRID - 1);
    }
    __syncthreads();

    // ---- last block finalizes (AvgNonZeroReducer) ----
    if (sIsLast) {
        __threadfence();
        float        s = 0.0f;
        unsigned int c = 0;
        if (t < GRID) {
            s = ((volatile float*)g_part)[t];
            c = ((volatile unsigned int*)g_cntp)[t];
        }
#pragma unroll
        for (int o = 16; o > 0; o >>= 1) {
            s += __shfl_xor_sync(0xffffffffu, s, o);
            c += __shfl_xor_sync(0xffffffffu, c, o);
        }
        if (t < GRID && lane == 0) { swsum[w] = s; swcnt[w] = c; }
        __syncthreads();
        if (t == 0) {
            float S = swsum[0] + swsum[1] + swsum[2] + swsum[3];
            unsigned int C = swcnt[0] + swcnt[1] + swcnt[2] + swcnt[3];
            out[0] = (C > 0) ? (S / (float)C) : 0.0f;
            g_done = 0;   // reset for next graph replay
        }
    }
}

extern "C" void kernel_launch(void* const* d_in, const int* in_sizes, int n_in,
                              void* d_out, int out_size) {
    const float* feat   = (const float*)d_in[0];   // [128, 4, 128] float32
    const int*   labels = (const int*)d_in[1];     // [128] int32
    float*       out    = (float*)d_out;           // scalar float32

    cudaFuncSetAttribute(fused_triplet_kernel,
                         cudaFuncAttributeMaxDynamicSharedMemorySize,
                         DYN_BYTES);
    fused_triplet_kernel<<<GRID, NT, DYN_BYTES>>>(feat, labels, out);
}